// round 3
// baseline (speedup 1.0000x reference)
#include <cuda_runtime.h>
#include <cuda_bf16.h>
#include <mma.h>

using namespace nvcuda;

// Problem constants
#define BATCH   4
#define SQ      4096
#define SK      1024
#define D_EMB   1024
#define D_CRUZ  768
#define N_HEADS 16
#define D_HEAD  64

// Scratch (static device allocations — allowed)
__device__ float g_q[BATCH * SQ * D_EMB];     // 64 MB
__device__ float g_k[BATCH * SK * D_EMB];     // 16 MB
__device__ float g_v[BATCH * SK * D_EMB];     // 16 MB
__device__ float g_attn[BATCH * SQ * D_EMB];  // 64 MB

// ---------------------------------------------------------------------------
// tf32 helpers
// ---------------------------------------------------------------------------
template <class Frag>
__device__ __forceinline__ void frag_to_tf32(Frag& f) {
#pragma unroll
    for (int i = 0; i < f.num_elements; i++) f.x[i] = wmma::__float_to_tf32(f.x[i]);
}

// ---------------------------------------------------------------------------
// GEMM: C[M,N] = A[M,K] @ W[K,N] + bias[N]   (all row-major fp32, tf32 compute)
// Block tile 64x64, K-tile 32, 256 threads (8 warps in 4x2).
// Requires: M%64==0, N%64==0, K%32==0 (true for all four projections).
// ---------------------------------------------------------------------------
__global__ __launch_bounds__(256)
void gemm_bias_tf32(const float* __restrict__ A, const float* __restrict__ W,
                    const float* __restrict__ bias, float* __restrict__ C,
                    int M, int N, int K) {
    __shared__ float sm[4864];                 // As: 64x40 (2560) | Bs: 32x72 (2304)
    float* As = sm;                            // ld 40
    float* Bs = sm + 2560;                     // ld 72

    const int tid  = threadIdx.x;
    const int warp = tid >> 5;
    const int wm   = warp >> 1;                // 0..3 -> rows wm*16
    const int wn   = warp & 1;                 // 0..1 -> cols wn*32
    const int bm   = blockIdx.y * 64;
    const int bn   = blockIdx.x * 64;

    wmma::fragment<wmma::accumulator, 16, 16, 8, float> acc[2];
    wmma::fill_fragment(acc[0], 0.0f);
    wmma::fill_fragment(acc[1], 0.0f);

    for (int k0 = 0; k0 < K; k0 += 32) {
        // Load A tile 64x32 (512 float4, 2 per thread)
#pragma unroll
        for (int i = 0; i < 2; i++) {
            int p   = tid + i * 256;           // 0..511
            int row = p >> 3;
            int col = (p & 7) * 4;
            float4 v = *reinterpret_cast<const float4*>(&A[(size_t)(bm + row) * K + k0 + col]);
            *reinterpret_cast<float4*>(&As[row * 40 + col]) = v;
        }
        // Load B tile 32x64 (512 float4, 2 per thread)
#pragma unroll
        for (int i = 0; i < 2; i++) {
            int p   = tid + i * 256;
            int row = p >> 4;
            int col = (p & 15) * 4;
            float4 v = *reinterpret_cast<const float4*>(&W[(size_t)(k0 + row) * N + bn + col]);
            *reinterpret_cast<float4*>(&Bs[row * 72 + col]) = v;
        }
        __syncthreads();

#pragma unroll
        for (int kk = 0; kk < 32; kk += 8) {
            wmma::fragment<wmma::matrix_a, 16, 16, 8, wmma::precision::tf32, wmma::row_major> a;
            wmma::load_matrix_sync(a, &As[wm * 16 * 40 + kk], 40);
            frag_to_tf32(a);
#pragma unroll
            for (int f = 0; f < 2; f++) {
                wmma::fragment<wmma::matrix_b, 16, 16, 8, wmma::precision::tf32, wmma::row_major> b;
                wmma::load_matrix_sync(b, &Bs[kk * 72 + wn * 32 + f * 16], 72);
                frag_to_tf32(b);
                wmma::mma_sync(acc[f], a, b, acc[f]);
            }
        }
        __syncthreads();
    }

    // Epilogue: stage C tile in smem (reuse sm, ld 72), add bias, write out
#pragma unroll
    for (int f = 0; f < 2; f++)
        wmma::store_matrix_sync(&sm[wm * 16 * 72 + wn * 32 + f * 16], acc[f], 72, wmma::mem_row_major);
    __syncthreads();

#pragma unroll
    for (int i = 0; i < 16; i++) {
        int p   = tid + i * 256;               // 0..4095
        int row = p >> 6;
        int col = p & 63;
        C[(size_t)(bm + row) * N + bn + col] = sm[row * 72 + col] + bias[bn + col];
    }
}

// ---------------------------------------------------------------------------
// Flash attention: per CTA handles one (b, h, 64-row q tile).
// q,k,v laid out [B, S, D]; head h occupies cols h*64..h*64+63.
// Streams K/V in 64-row tiles; online softmax; tf32 wmma for S=QK^T and P@V.
// O-rescale merged into the accumulate pass (Os = Os*alpha + PV).
// ---------------------------------------------------------------------------
#define ATTN_SMEM_FLOATS (6 * 4608 + 256)
#define ATTN_SMEM_BYTES  (ATTN_SMEM_FLOATS * 4)

__global__ __launch_bounds__(256)
void attn_flash_tf32(const float* __restrict__ qg, const float* __restrict__ kg,
                     const float* __restrict__ vg, float* __restrict__ og) {
    extern __shared__ float smem[];
    float* Qs  = smem;              // 64 x 72
    float* Ks  = Qs  + 4608;        // 64 x 72
    float* Vs  = Ks  + 4608;        // 64 x 72
    float* Ps  = Vs  + 4608;        // 64 x 72
    float* PVs = Ps  + 4608;        // 64 x 72
    float* Os  = PVs + 4608;        // 64 x 72
    float* mrow = Os + 4608;        // 64
    float* lrow = mrow + 64;        // 64
    float* arow = lrow + 64;        // 64 (per-row alpha for merged rescale)

    const int tid  = threadIdx.x;
    const int warp = tid >> 5;
    const int wm   = warp >> 1;
    const int wn   = warp & 1;

    const int q0 = blockIdx.x * 64;
    const int h  = blockIdx.y;
    const int b  = blockIdx.z;
    const float scale = 0.125f;     // 1/sqrt(64)

    // Load Q tile (64x64) + init state
#pragma unroll
    for (int i = 0; i < 4; i++) {
        int p   = tid + i * 256;    // 0..1023 float4 slots
        int row = p >> 4;
        int col = (p & 15) * 4;
        float4 v = *reinterpret_cast<const float4*>(
            &qg[((size_t)(b * SQ + q0 + row)) * D_EMB + h * D_HEAD + col]);
        *reinterpret_cast<float4*>(&Qs[row * 72 + col]) = v;
    }
    for (int i = tid; i < 64 * 72; i += 256) Os[i] = 0.0f;
    if (tid < 64) { mrow[tid] = -1e30f; lrow[tid] = 0.0f; arow[tid] = 1.0f; }
    __syncthreads();

    for (int kt = 0; kt < SK / 64; kt++) {
        const int k0 = kt * 64;
        // Load K and V tiles (64x64 each)
#pragma unroll
        for (int i = 0; i < 4; i++) {
            int p   = tid + i * 256;
            int row = p >> 4;
            int col = (p & 15) * 4;
            size_t gidx = ((size_t)(b * SK + k0 + row)) * D_EMB + h * D_HEAD + col;
            *reinterpret_cast<float4*>(&Ks[row * 72 + col]) =
                *reinterpret_cast<const float4*>(&kg[gidx]);
            *reinterpret_cast<float4*>(&Vs[row * 72 + col]) =
                *reinterpret_cast<const float4*>(&vg[gidx]);
        }
        __syncthreads();

        // S = scale * Q @ K^T  (64x64x64)
        {
            wmma::fragment<wmma::accumulator, 16, 16, 8, float> sacc[2];
            wmma::fill_fragment(sacc[0], 0.0f);
            wmma::fill_fragment(sacc[1], 0.0f);
#pragma unroll
            for (int kk = 0; kk < 64; kk += 8) {
                wmma::fragment<wmma::matrix_a, 16, 16, 8, wmma::precision::tf32, wmma::row_major> a;
                wmma::load_matrix_sync(a, &Qs[wm * 16 * 72 + kk], 72);
                frag_to_tf32(a);
#pragma unroll
                for (int f = 0; f < 2; f++) {
                    // B = K^T: col_major view of K tile
                    wmma::fragment<wmma::matrix_b, 16, 16, 8, wmma::precision::tf32, wmma::col_major> kb;
                    wmma::load_matrix_sync(kb, &Ks[(wn * 32 + f * 16) * 72 + kk], 72);
                    frag_to_tf32(kb);
                    wmma::mma_sync(sacc[f], a, kb, sacc[f]);
                }
            }
#pragma unroll
            for (int f = 0; f < 2; f++) {
#pragma unroll
                for (int e = 0; e < sacc[f].num_elements; e++) sacc[f].x[e] *= scale;
                wmma::store_matrix_sync(&Ps[wm * 16 * 72 + wn * 32 + f * 16], sacc[f],
                                        72, wmma::mem_row_major);
            }
        }
        __syncthreads();

        // Online softmax update: 4 threads per row, 16 cols each.
        // Stores per-row alpha; O-rescale deferred to the accumulate pass.
        {
            const int row = tid >> 2;
            const int sub = tid & 3;
            const int c0  = sub * 16;
            float mx = -1e30f;
#pragma unroll
            for (int c = 0; c < 16; c++) mx = fmaxf(mx, Ps[row * 72 + c0 + c]);
            mx = fmaxf(mx, __shfl_xor_sync(0xffffffffu, mx, 1));
            mx = fmaxf(mx, __shfl_xor_sync(0xffffffffu, mx, 2));
            const float mold = mrow[row];
            const float mnew = fmaxf(mold, mx);
            float sum = 0.0f;
#pragma unroll
            for (int c = 0; c < 16; c++) {
                float p = __expf(Ps[row * 72 + c0 + c] - mnew);
                Ps[row * 72 + c0 + c] = p;
                sum += p;
            }
            sum += __shfl_xor_sync(0xffffffffu, sum, 1);
            sum += __shfl_xor_sync(0xffffffffu, sum, 2);
            const float alpha = __expf(mold - mnew);
            if (sub == 0) {
                mrow[row] = mnew;
                lrow[row] = lrow[row] * alpha + sum;
                arow[row] = alpha;
            }
        }
        __syncthreads();

        // PV = P @ V  (64x64x64)
        {
            wmma::fragment<wmma::accumulator, 16, 16, 8, float> pacc[2];
            wmma::fill_fragment(pacc[0], 0.0f);
            wmma::fill_fragment(pacc[1], 0.0f);
#pragma unroll
            for (int kk = 0; kk < 64; kk += 8) {
                wmma::fragment<wmma::matrix_a, 16, 16, 8, wmma::precision::tf32, wmma::row_major> a;
                wmma::load_matrix_sync(a, &Ps[wm * 16 * 72 + kk], 72);
                frag_to_tf32(a);
#pragma unroll
                for (int f = 0; f < 2; f++) {
                    wmma::fragment<wmma::matrix_b, 16, 16, 8, wmma::precision::tf32, wmma::row_major> vb;
                    wmma::load_matrix_sync(vb, &Vs[kk * 72 + wn * 32 + f * 16], 72);
                    frag_to_tf32(vb);
                    wmma::mma_sync(pacc[f], a, vb, pacc[f]);
                }
            }
#pragma unroll
            for (int f = 0; f < 2; f++)
                wmma::store_matrix_sync(&PVs[wm * 16 * 72 + wn * 32 + f * 16], pacc[f],
                                        72, wmma::mem_row_major);
        }
        __syncthreads();

        // O = O * alpha + PV (merged rescale + accumulate, single pass)
#pragma unroll
        for (int i = 0; i < 16; i++) {
            int p   = tid + i * 256;
            int row = p >> 6;
            int col = p & 63;
            Os[row * 72 + col] = Os[row * 72 + col] * arow[row] + PVs[row * 72 + col];
        }
        __syncthreads();
    }

    // Final: write O / l
#pragma unroll
    for (int i = 0; i < 16; i++) {
        int p   = tid + i * 256;
        int row = p >> 6;
        int col = p & 63;
        og[((size_t)(b * SQ + q0 + row)) * D_EMB + h * D_HEAD + col] =
            Os[row * 72 + col] / lrow[row];
    }
}

// ---------------------------------------------------------------------------
// Launcher
// ---------------------------------------------------------------------------
extern "C" void kernel_launch(void* const* d_in, const int* in_sizes, int n_in,
                              void* d_out, int out_size) {
    const float* x  = (const float*)d_in[0];
    const float* y  = (const float*)d_in[1];
    const float* Wq = (const float*)d_in[2];
    const float* bq = (const float*)d_in[3];
    const float* Wk = (const float*)d_in[4];
    const float* bk = (const float*)d_in[5];
    const float* Wv = (const float*)d_in[6];
    const float* bv = (const float*)d_in[7];
    const float* Wo = (const float*)d_in[8];
    const float* bo = (const float*)d_in[9];
    float* out = (float*)d_out;

    float *gq, *gk, *gv, *ga;
    cudaGetSymbolAddress((void**)&gq, g_q);
    cudaGetSymbolAddress((void**)&gk, g_k);
    cudaGetSymbolAddress((void**)&gv, g_v);
    cudaGetSymbolAddress((void**)&ga, g_attn);

    cudaFuncSetAttribute(attn_flash_tf32,
                         cudaFuncAttributeMaxDynamicSharedMemorySize, ATTN_SMEM_BYTES);

    const dim3 blk(256);

    // Projections
    gemm_bias_tf32<<<dim3(D_EMB / 64, (BATCH * SQ) / 64), blk>>>(x, Wq, bq, gq,
        BATCH * SQ, D_EMB, D_EMB);
    gemm_bias_tf32<<<dim3(D_EMB / 64, (BATCH * SK) / 64), blk>>>(y, Wk, bk, gk,
        BATCH * SK, D_EMB, D_CRUZ);
    gemm_bias_tf32<<<dim3(D_EMB / 64, (BATCH * SK) / 64), blk>>>(y, Wv, bv, gv,
        BATCH * SK, D_EMB, D_CRUZ);

    // Attention
    attn_flash_tf32<<<dim3(SQ / 64, N_HEADS, BATCH), blk, ATTN_SMEM_BYTES>>>(gq, gk, gv, ga);

    // Output projection
    gemm_bias_tf32<<<dim3(D_EMB / 64, (BATCH * SQ) / 64), blk>>>(ga, Wo, bo, out,
        BATCH * SQ, D_EMB, D_EMB);
}

// round 5
// speedup vs baseline: 1.1253x; 1.1253x over previous
#include <cuda_runtime.h>
#include <cuda_bf16.h>
#include <mma.h>
#include <cstdint>

using namespace nvcuda;

// Problem constants
#define BATCH   4
#define SQ      4096
#define SK      1024
#define D_EMB   1024
#define D_CRUZ  768
#define N_HEADS 16
#define D_HEAD  64

// Scratch (static device allocations — allowed)
__device__ float g_q[BATCH * SQ * D_EMB];     // 64 MB
__device__ float g_k[BATCH * SK * D_EMB];     // 16 MB
__device__ float g_v[BATCH * SK * D_EMB];     // 16 MB
__device__ float g_attn[BATCH * SQ * D_EMB];  // 64 MB

// ---------------------------------------------------------------------------
// helpers
// ---------------------------------------------------------------------------
template <class Frag>
__device__ __forceinline__ void frag_to_tf32(Frag& f) {
#pragma unroll
    for (int i = 0; i < f.num_elements; i++) f.x[i] = wmma::__float_to_tf32(f.x[i]);
}

__device__ __forceinline__ void cp_async16(float* dst_smem, const float* src) {
    unsigned int d = (unsigned int)__cvta_generic_to_shared(dst_smem);
    asm volatile("cp.async.ca.shared.global [%0], [%1], 16;\n" :: "r"(d), "l"(src));
}
__device__ __forceinline__ void cp_commit() {
    asm volatile("cp.async.commit_group;\n");
}
template <int N>
__device__ __forceinline__ void cp_wait() {
    asm volatile("cp.async.wait_group %0;\n" :: "n"(N));
}

// ---------------------------------------------------------------------------
// GEMM v2: C[M,N] = A[M,K] @ W[K,N] + bias[N]  (tf32, 128x128x32 tiles,
// 2-stage cp.async double buffering, 256 threads / 8 warps in 4x2,
// each warp computes 32x64 via acc[2][4] m16n16k8 fragments)
// Requires M%128==0, N%128==0, K%32==0 (holds for all four projections).
// ---------------------------------------------------------------------------
#define BM 128
#define BN 128
#define BK 32
#define LDA 40                     // BK + 8
#define LDB 136                    // BN + 8
#define A_STG (BM * LDA)           // 5120 floats
#define B_STG (BK * LDB)           // 4352 floats
#define STG_FLOATS (A_STG + B_STG) // 9472
#define GEMM_SMEM_FLOATS (2 * STG_FLOATS)
#define GEMM_SMEM_BYTES  (GEMM_SMEM_FLOATS * 4)   // 75776

__global__ __launch_bounds__(256)
void gemm_bias_tf32_v2(const float* __restrict__ A, const float* __restrict__ W,
                       const float* __restrict__ bias, float* __restrict__ C,
                       int M, int N, int K) {
    extern __shared__ float sm[];
    const int tid  = threadIdx.x;
    const int warp = tid >> 5;
    const int wm   = warp >> 1;    // 0..3 -> 32-row band
    const int wn   = warp & 1;     // 0..1 -> 64-col band
    const int bm   = blockIdx.y * BM;
    const int bn   = blockIdx.x * BN;

    wmma::fragment<wmma::accumulator, 16, 16, 8, float> acc[2][4];
#pragma unroll
    for (int r = 0; r < 2; r++)
#pragma unroll
        for (int c = 0; c < 4; c++) wmma::fill_fragment(acc[r][c], 0.0f);

    auto issue = [&](int kt, int buf) {
        float* As = sm + buf * STG_FLOATS;
        float* Bs = As + A_STG;
        const float* Ag = A + (size_t)bm * K + kt * BK;
        const float* Wg = W + (size_t)(kt * BK) * N + bn;
#pragma unroll
        for (int i = 0; i < 4; i++) {              // A: 128x32 = 1024 float4
            int p   = tid + i * 256;
            int row = p >> 3;
            int col = (p & 7) * 4;
            cp_async16(&As[row * LDA + col], Ag + (size_t)row * K + col);
        }
#pragma unroll
        for (int i = 0; i < 4; i++) {              // B: 32x128 = 1024 float4
            int p   = tid + i * 256;
            int row = p >> 5;
            int col = (p & 31) * 4;
            cp_async16(&Bs[row * LDB + col], Wg + (size_t)row * N + col);
        }
    };

    const int NK = K / BK;
    issue(0, 0);
    cp_commit();

    for (int kt = 0; kt < NK; kt++) {
        if (kt + 1 < NK) {
            issue(kt + 1, (kt + 1) & 1);
            cp_commit();
            cp_wait<1>();                          // tile kt has landed
        } else {
            cp_wait<0>();
        }
        __syncthreads();

        float* As = sm + (kt & 1) * STG_FLOATS;
        float* Bs = As + A_STG;
#pragma unroll
        for (int kk = 0; kk < BK; kk += 8) {
            wmma::fragment<wmma::matrix_a, 16, 16, 8, wmma::precision::tf32, wmma::row_major> a[2];
#pragma unroll
            for (int r = 0; r < 2; r++) {
                wmma::load_matrix_sync(a[r], &As[(wm * 32 + r * 16) * LDA + kk], LDA);
                frag_to_tf32(a[r]);
            }
#pragma unroll
            for (int c = 0; c < 4; c++) {
                wmma::fragment<wmma::matrix_b, 16, 16, 8, wmma::precision::tf32, wmma::row_major> b;
                wmma::load_matrix_sync(b, &Bs[kk * LDB + wn * 64 + c * 16], LDB);
                frag_to_tf32(b);
#pragma unroll
                for (int r = 0; r < 2; r++)
                    wmma::mma_sync(acc[r][c], a[r], b, acc[r][c]);
            }
        }
        __syncthreads();
    }

    // Epilogue: stage 128x128 tile in smem (ld LDB), add bias, vector store
    float* Cs = sm;                                // 128*136 = 17408 <= smem
#pragma unroll
    for (int r = 0; r < 2; r++)
#pragma unroll
        for (int c = 0; c < 4; c++)
            wmma::store_matrix_sync(&Cs[(wm * 32 + r * 16) * LDB + wn * 64 + c * 16],
                                    acc[r][c], LDB, wmma::mem_row_major);
    __syncthreads();

#pragma unroll
    for (int i = 0; i < 16; i++) {                 // 4096 float4
        int p   = tid + i * 256;
        int row = p >> 5;
        int col = (p & 31) * 4;
        float4 v = *reinterpret_cast<float4*>(&Cs[row * LDB + col]);
        float4 bb = *reinterpret_cast<const float4*>(&bias[bn + col]);
        v.x += bb.x; v.y += bb.y; v.z += bb.z; v.w += bb.w;
        *reinterpret_cast<float4*>(&C[(size_t)(bm + row) * N + bn + col]) = v;
    }
}

// ---------------------------------------------------------------------------
// Flash attention: per CTA one (b, h, 64-row q tile). Q pre-scaled by 1/8.
// PV accumulates directly into the O smem tile via accumulator load (no PVs
// buffer). smem ~91KB -> 2 CTAs/SM.
// ---------------------------------------------------------------------------
#define ATTN_SMEM_FLOATS (5 * 4608 + 256)
#define ATTN_SMEM_BYTES  (ATTN_SMEM_FLOATS * 4)

__global__ __launch_bounds__(256)
void attn_flash_tf32(const float* __restrict__ qg, const float* __restrict__ kg,
                     const float* __restrict__ vg, float* __restrict__ og) {
    extern __shared__ float smem[];
    float* Qs  = smem;              // 64 x 72
    float* Ks  = Qs  + 4608;        // 64 x 72
    float* Vs  = Ks  + 4608;        // 64 x 72
    float* Ps  = Vs  + 4608;        // 64 x 72
    float* Os  = Ps  + 4608;        // 64 x 72
    float* mrow = Os + 4608;        // 64
    float* lrow = mrow + 64;        // 64
    float* arow = lrow + 64;        // 64

    const int tid  = threadIdx.x;
    const int warp = tid >> 5;
    const int wm   = warp >> 1;
    const int wn   = warp & 1;

    const int q0 = blockIdx.x * 64;
    const int h  = blockIdx.y;
    const int b  = blockIdx.z;
    const float scale = 0.125f;     // 1/sqrt(64), folded into Q

    // Load Q tile (64x64), pre-scaled; init state
#pragma unroll
    for (int i = 0; i < 4; i++) {
        int p   = tid + i * 256;
        int row = p >> 4;
        int col = (p & 15) * 4;
        float4 v = *reinterpret_cast<const float4*>(
            &qg[((size_t)(b * SQ + q0 + row)) * D_EMB + h * D_HEAD + col]);
        v.x *= scale; v.y *= scale; v.z *= scale; v.w *= scale;
        *reinterpret_cast<float4*>(&Qs[row * 72 + col]) = v;
    }
    for (int i = tid; i < 64 * 72; i += 256) Os[i] = 0.0f;
    if (tid < 64) { mrow[tid] = -1e30f; lrow[tid] = 0.0f; arow[tid] = 1.0f; }
    __syncthreads();

    for (int kt = 0; kt < SK / 64; kt++) {
        const int k0 = kt * 64;
#pragma unroll
        for (int i = 0; i < 4; i++) {
            int p   = tid + i * 256;
            int row = p >> 4;
            int col = (p & 15) * 4;
            size_t gidx = ((size_t)(b * SK + k0 + row)) * D_EMB + h * D_HEAD + col;
            *reinterpret_cast<float4*>(&Ks[row * 72 + col]) =
                *reinterpret_cast<const float4*>(&kg[gidx]);
            *reinterpret_cast<float4*>(&Vs[row * 72 + col]) =
                *reinterpret_cast<const float4*>(&vg[gidx]);
        }
        __syncthreads();

        // S = Q @ K^T (Q pre-scaled)
        {
            wmma::fragment<wmma::accumulator, 16, 16, 8, float> sacc[2];
            wmma::fill_fragment(sacc[0], 0.0f);
            wmma::fill_fragment(sacc[1], 0.0f);
#pragma unroll
            for (int kk = 0; kk < 64; kk += 8) {
                wmma::fragment<wmma::matrix_a, 16, 16, 8, wmma::precision::tf32, wmma::row_major> a;
                wmma::load_matrix_sync(a, &Qs[wm * 16 * 72 + kk], 72);
                frag_to_tf32(a);
#pragma unroll
                for (int f = 0; f < 2; f++) {
                    wmma::fragment<wmma::matrix_b, 16, 16, 8, wmma::precision::tf32, wmma::col_major> kb;
                    wmma::load_matrix_sync(kb, &Ks[(wn * 32 + f * 16) * 72 + kk], 72);
                    frag_to_tf32(kb);
                    wmma::mma_sync(sacc[f], a, kb, sacc[f]);
                }
            }
#pragma unroll
            for (int f = 0; f < 2; f++)
                wmma::store_matrix_sync(&Ps[wm * 16 * 72 + wn * 32 + f * 16], sacc[f],
                                        72, wmma::mem_row_major);
        }
        __syncthreads();

        // Online softmax (4 threads/row, 16 cols each); alpha saved per row
        {
            const int row = tid >> 2;
            const int sub = tid & 3;
            const int c0  = sub * 16;
            float mx = -1e30f;
#pragma unroll
            for (int c = 0; c < 16; c++) mx = fmaxf(mx, Ps[row * 72 + c0 + c]);
            mx = fmaxf(mx, __shfl_xor_sync(0xffffffffu, mx, 1));
            mx = fmaxf(mx, __shfl_xor_sync(0xffffffffu, mx, 2));
            const float mold = mrow[row];
            const float mnew = fmaxf(mold, mx);
            float sum = 0.0f;
#pragma unroll
            for (int c = 0; c < 16; c++) {
                float p = __expf(Ps[row * 72 + c0 + c] - mnew);
                Ps[row * 72 + c0 + c] = p;
                sum += p;
            }
            sum += __shfl_xor_sync(0xffffffffu, sum, 1);
            sum += __shfl_xor_sync(0xffffffffu, sum, 2);
            const float alpha = __expf(mold - mnew);
            if (sub == 0) {
                mrow[row] = mnew;
                lrow[row] = lrow[row] * alpha + sum;
                arow[row] = alpha;
            }
        }
        __syncthreads();

        // Rescale O in smem, then PV mma accumulates directly into O tile
#pragma unroll
        for (int i = 0; i < 16; i++) {
            int p   = tid + i * 256;
            int row = p >> 6;
            int col = p & 63;
            Os[row * 72 + col] *= arow[row];
        }
        __syncthreads();

        {
            wmma::fragment<wmma::accumulator, 16, 16, 8, float> pacc[2];
#pragma unroll
            for (int f = 0; f < 2; f++)
                wmma::load_matrix_sync(pacc[f], &Os[wm * 16 * 72 + wn * 32 + f * 16],
                                       72, wmma::mem_row_major);
#pragma unroll
            for (int kk = 0; kk < 64; kk += 8) {
                wmma::fragment<wmma::matrix_a, 16, 16, 8, wmma::precision::tf32, wmma::row_major> a;
                wmma::load_matrix_sync(a, &Ps[wm * 16 * 72 + kk], 72);
                frag_to_tf32(a);
#pragma unroll
                for (int f = 0; f < 2; f++) {
                    wmma::fragment<wmma::matrix_b, 16, 16, 8, wmma::precision::tf32, wmma::row_major> vb;
                    wmma::load_matrix_sync(vb, &Vs[kk * 72 + wn * 32 + f * 16], 72);
                    frag_to_tf32(vb);
                    wmma::mma_sync(pacc[f], a, vb, pacc[f]);
                }
            }
#pragma unroll
            for (int f = 0; f < 2; f++)
                wmma::store_matrix_sync(&Os[wm * 16 * 72 + wn * 32 + f * 16], pacc[f],
                                        72, wmma::mem_row_major);
        }
        __syncthreads();
    }

    // Final: write O / l
#pragma unroll
    for (int i = 0; i < 16; i++) {
        int p   = tid + i * 256;
        int row = p >> 6;
        int col = p & 63;
        og[((size_t)(b * SQ + q0 + row)) * D_EMB + h * D_HEAD + col] =
            Os[row * 72 + col] / lrow[row];
    }
}

// ---------------------------------------------------------------------------
// Launcher
// ---------------------------------------------------------------------------
extern "C" void kernel_launch(void* const* d_in, const int* in_sizes, int n_in,
                              void* d_out, int out_size) {
    const float* x  = (const float*)d_in[0];
    const float* y  = (const float*)d_in[1];
    const float* Wq = (const float*)d_in[2];
    const float* bq = (const float*)d_in[3];
    const float* Wk = (const float*)d_in[4];
    const float* bk = (const float*)d_in[5];
    const float* Wv = (const float*)d_in[6];
    const float* bv = (const float*)d_in[7];
    const float* Wo = (const float*)d_in[8];
    const float* bo = (const float*)d_in[9];
    float* out = (float*)d_out;

    float *gq, *gk, *gv, *ga;
    cudaGetSymbolAddress((void**)&gq, g_q);
    cudaGetSymbolAddress((void**)&gk, g_k);
    cudaGetSymbolAddress((void**)&gv, g_v);
    cudaGetSymbolAddress((void**)&ga, g_attn);

    cudaFuncSetAttribute(gemm_bias_tf32_v2,
                         cudaFuncAttributeMaxDynamicSharedMemorySize, GEMM_SMEM_BYTES);
    cudaFuncSetAttribute(attn_flash_tf32,
                         cudaFuncAttributeMaxDynamicSharedMemorySize, ATTN_SMEM_BYTES);

    const dim3 blk(256);

    // Projections (M,N multiples of 128; K multiples of 32)
    gemm_bias_tf32_v2<<<dim3(D_EMB / BN, (BATCH * SQ) / BM), blk, GEMM_SMEM_BYTES>>>(
        x, Wq, bq, gq, BATCH * SQ, D_EMB, D_EMB);
    gemm_bias_tf32_v2<<<dim3(D_EMB / BN, (BATCH * SK) / BM), blk, GEMM_SMEM_BYTES>>>(
        y, Wk, bk, gk, BATCH * SK, D_EMB, D_CRUZ);
    gemm_bias_tf32_v2<<<dim3(D_EMB / BN, (BATCH * SK) / BM), blk, GEMM_SMEM_BYTES>>>(
        y, Wv, bv, gv, BATCH * SK, D_EMB, D_CRUZ);

    // Attention
    attn_flash_tf32<<<dim3(SQ / 64, N_HEADS, BATCH), blk, ATTN_SMEM_BYTES>>>(gq, gk, gv, ga);

    // Output projection
    gemm_bias_tf32_v2<<<dim3(D_EMB / BN, (BATCH * SQ) / BM), blk, GEMM_SMEM_BYTES>>>(
        ga, Wo, bo, out, BATCH * SQ, D_EMB, D_EMB);
}